// round 1
// baseline (speedup 1.0000x reference)
#include <cuda_runtime.h>

// AttentionDownsampler: hr_feats (8,384,112,112) f32, non-overlapping 7x7 patches
// -> 16x16 tiles. Per tile: logits[p]=dot(patch[p,:],aw)+ab ; softmax over
// (logits*mask*w+b) ; out[c] = sum_p patch[p,c]*attn[p]. Output (8,384,16,16) f32.

#define DIMC   384
#define KWIN   7
#define PP     49          // KWIN*KWIN
#define FINALN 16
#define HW     112
#define CPLANE (HW*HW)     // 12544
#define TPB    256

__global__ __launch_bounds__(TPB)
void attn_ds_kernel(const float* __restrict__ hr,
                    const float* __restrict__ du,
                    const float* __restrict__ aw,
                    const float* __restrict__ ab,
                    const float* __restrict__ wv,
                    const float* __restrict__ bv,
                    float* __restrict__ out)
{
    extern __shared__ float sp[];          // [DIMC][PP] patch, 75264 B
    __shared__ float slog[PP];             // raw logits
    __shared__ float sattn[64];            // masked logits -> attn weights

    const int wt = blockIdx.x;             // w tile 0..15
    const int h  = blockIdx.y;             // h tile 0..15
    const int bb = blockIdx.z;             // batch 0..7
    const int t  = threadIdx.x;
    const int warp = t >> 5;
    const int lane = t & 31;

    // ---- load patch into smem: sp[c*49 + kr*7 + kc] ----
    const float* base = hr + (size_t)bb * DIMC * CPLANE + (h * KWIN) * HW + wt * KWIN;
    #pragma unroll 4
    for (int i = t; i < DIMC * PP; i += TPB) {
        const int c  = i / PP;
        const int p  = i - c * PP;
        const int kr = p / KWIN;
        const int kc = p - kr * KWIN;
        sp[i] = base[(size_t)c * CPLANE + kr * HW + kc];
    }

    // aw cached in registers per lane (c = lane + 32k), straight from global (L1)
    float awv[DIMC / 32];
    #pragma unroll
    for (int k = 0; k < DIMC / 32; ++k) awv[k] = aw[lane + 32 * k];

    __syncthreads();

    // ---- pass 1: logits[p] = sum_c sp[c][p]*aw[c]  (warp per p, stride-49 = conflict-free)
    for (int p = warp; p < PP; p += TPB / 32) {
        float acc = 0.f;
        #pragma unroll
        for (int k = 0; k < DIMC / 32; ++k)
            acc = fmaf(sp[(lane + 32 * k) * PP + p], awv[k], acc);
        #pragma unroll
        for (int o = 16; o; o >>= 1) acc += __shfl_xor_sync(0xffffffffu, acc, o);
        if (lane == 0) slog[p] = acc;
    }
    __syncthreads();

    // ---- masked logits ----
    const float maskv = (du[(bb * FINALN + h) * FINALN + wt] > 0.2f) ? 1.f : 0.f;
    if (t < PP) {
        const float ml = (slog[t] + ab[0]) * maskv * wv[t] + bv[t];
        sattn[t] = ml;
    }
    __syncthreads();

    // ---- softmax over 49 (warp 0) ----
    if (warp == 0) {
        const bool hi = (lane + 32) < PP;
        float v1 = sattn[lane];
        float v2 = hi ? sattn[lane + 32] : -1e30f;
        float m = fmaxf(v1, v2);
        #pragma unroll
        for (int o = 16; o; o >>= 1) m = fmaxf(m, __shfl_xor_sync(0xffffffffu, m, o));
        float e1 = __expf(v1 - m);
        float e2 = hi ? __expf(v2 - m) : 0.f;
        float s = e1 + e2;
        #pragma unroll
        for (int o = 16; o; o >>= 1) s += __shfl_xor_sync(0xffffffffu, s, o);
        const float inv = __frcp_rn(s);
        sattn[lane] = e1 * inv;
        if (hi) sattn[lane + 32] = e2 * inv;
    }
    __syncthreads();

    // ---- pass 2: out[c] = sum_p sp[c][p]*attn[p], attn register-cached ----
    float a[PP];
    #pragma unroll
    for (int p = 0; p < PP; ++p) a[p] = sattn[p];

    for (int c = t; c < DIMC; c += TPB) {
        const float* row = sp + c * PP;
        float acc = 0.f;
        #pragma unroll
        for (int p = 0; p < PP; ++p) acc = fmaf(row[p], a[p], acc);
        out[(((size_t)bb * DIMC + c) * FINALN + h) * FINALN + wt] = acc;
    }
}

extern "C" void kernel_launch(void* const* d_in, const int* in_sizes, int n_in,
                              void* d_out, int out_size)
{
    const float* hr = (const float*)d_in[0];   // (8,384,112,112)
    // d_in[1] = guidance (unused)
    const float* du = (const float*)d_in[2];   // (8,16,16,1)
    const float* aw = (const float*)d_in[3];   // (384,)
    const float* ab = (const float*)d_in[4];   // (1,)
    const float* wv = (const float*)d_in[5];   // (7,7)
    const float* bv = (const float*)d_in[6];   // (7,7)
    float* out = (float*)d_out;                // (8,384,16,16)

    const int smem = DIMC * PP * (int)sizeof(float);   // 75264 B
    static bool attr_set = false;
    if (!attr_set) {
        cudaFuncSetAttribute(attn_ds_kernel,
                             cudaFuncAttributeMaxDynamicSharedMemorySize, smem);
        attr_set = true;
    }

    dim3 grid(FINALN, FINALN, 8);
    attn_ds_kernel<<<grid, TPB, smem>>>(hr, du, aw, ab, wv, bv, out);
}

// round 3
// speedup vs baseline: 1.1284x; 1.1284x over previous
#include <cuda_runtime.h>

// AttentionDownsampler: hr_feats (8,384,112,112) f32, non-overlapping 7x7 patches
// -> 16x16 tiles. logits[p]=dot(patch[p,:],aw)+ab ; softmax((logits*mask)*w+b) ;
// out[b,c,h,w] = sum_p patch[p,c]*attn[p]. Output (8,384,16,16) f32.
//
// R2 (resubmit after infra timeout): logit dot-product fused into the
// global->smem load loop (no separate smem pass), fixed per-thread (kr,kc)
// so the hot loop has zero div/mod.

#define DIMC   384
#define KWIN   7
#define PP     49
#define FINALN 16
#define HW     112
#define CPLANE (HW*HW)     // 12544
#define TPB    256
#define CSTEP  4           // TPB/64 channels per load iteration
#define NITER  (DIMC/CSTEP)

__global__ __launch_bounds__(TPB)
void attn_ds_kernel(const float* __restrict__ hr,
                    const float* __restrict__ du,
                    const float* __restrict__ aw,
                    const float* __restrict__ ab,
                    const float* __restrict__ wv,
                    const float* __restrict__ bv,
                    float* __restrict__ out)
{
    extern __shared__ float sp[];          // [DIMC][PP] patch, 75264 B
    __shared__ float saw[DIMC];
    __shared__ float sred[TPB];
    __shared__ float sattn[64];

    const int wt = blockIdx.x;
    const int h  = blockIdx.y;
    const int bb = blockIdx.z;
    const int t  = threadIdx.x;
    const int warp = t >> 5;
    const int lane = t & 31;

    // stage aw in smem (broadcast reads in the hot loop)
    for (int i = t; i < DIMC; i += TPB) saw[i] = aw[i];
    __syncthreads();

    // ---- fused load + logit accumulation ----
    // thread -> fixed patch slot p = t&63 (49 valid), channel c = (t>>6) + 4*j
    const int p   = t & 63;
    const int c0  = t >> 6;
    const bool act = (p < PP);
    const int kr  = p / KWIN;          // computed once, p is loop-invariant
    const int kc  = p - kr * KWIN;

    const float* gp = hr + (size_t)bb * DIMC * CPLANE
                         + (size_t)c0 * CPLANE
                         + (h * KWIN + kr) * HW + (wt * KWIN + kc);
    float* spp = sp + c0 * PP + p;

    float lacc = 0.f;
    #pragma unroll 8
    for (int j = 0; j < NITER; ++j) {
        const float awc = saw[c0 + CSTEP * j];          // warp-uniform broadcast
        if (act) {
            const float v = gp[j * (CSTEP * CPLANE)];
            spp[j * (CSTEP * PP)] = v;
            lacc = fmaf(v, awc, lacc);
        }
    }

    sred[t] = lacc;
    __syncthreads();

    // ---- combine 4 partials per p, apply bias/mask/affine ----
    if (t < 64) {
        const float l = sred[t] + sred[t + 64] + sred[t + 128] + sred[t + 192];
        if (t < PP) {
            const float maskv = (du[(bb * FINALN + h) * FINALN + wt] > 0.2f) ? 1.f : 0.f;
            sattn[t] = (l + ab[0]) * maskv * wv[t] + bv[t];
        }
    }
    __syncthreads();

    // ---- softmax over 49 (warp 0) ----
    if (warp == 0) {
        const bool hi = (lane + 32) < PP;
        float v1 = sattn[lane];
        float v2 = hi ? sattn[lane + 32] : -1e30f;
        float m = fmaxf(v1, v2);
        #pragma unroll
        for (int o = 16; o; o >>= 1) m = fmaxf(m, __shfl_xor_sync(0xffffffffu, m, o));
        float e1 = __expf(v1 - m);
        float e2 = hi ? __expf(v2 - m) : 0.f;
        float s = e1 + e2;
        #pragma unroll
        for (int o = 16; o; o >>= 1) s += __shfl_xor_sync(0xffffffffu, s, o);
        const float inv = __frcp_rn(s);
        sattn[lane] = e1 * inv;
        if (hi) sattn[lane + 32] = e2 * inv;
    }
    __syncthreads();

    // ---- output: out[c] = sum_p sp[c][p]*attn[p], attn register-cached ----
    float a[PP];
    #pragma unroll
    for (int q = 0; q < PP; ++q) a[q] = sattn[q];

    for (int c = t; c < DIMC; c += TPB) {
        const float* row = sp + c * PP;
        float acc = 0.f;
        #pragma unroll
        for (int q = 0; q < PP; ++q) acc = fmaf(row[q], a[q], acc);
        out[(((size_t)bb * DIMC + c) * FINALN + h) * FINALN + wt] = acc;
    }
}

extern "C" void kernel_launch(void* const* d_in, const int* in_sizes, int n_in,
                              void* d_out, int out_size)
{
    const float* hr = (const float*)d_in[0];   // (8,384,112,112)
    const float* du = (const float*)d_in[2];   // (8,16,16,1)
    const float* aw = (const float*)d_in[3];   // (384,)
    const float* ab = (const float*)d_in[4];   // (1,)
    const float* wv = (const float*)d_in[5];   // (7,7)
    const float* bv = (const float*)d_in[6];   // (7,7)
    float* out = (float*)d_out;                // (8,384,16,16)

    const int smem = DIMC * PP * (int)sizeof(float);   // 75264 B
    static bool attr_set = false;
    if (!attr_set) {
        cudaFuncSetAttribute(attn_ds_kernel,
                             cudaFuncAttributeMaxDynamicSharedMemorySize, smem);
        attr_set = true;
    }

    dim3 grid(FINALN, FINALN, 8);
    attn_ds_kernel<<<grid, TPB, smem>>>(hr, du, aw, ab, wv, bv, out);
}

// round 10
// speedup vs baseline: 1.4149x; 1.2539x over previous
#include <cuda_runtime.h>

// AttentionDownsampler (8,384,112,112) f32 -> (8,384,16,16) f32.
// R4 (7th submit; prior runs hit broker GPUAcquisitionTimeout):
// two-kernel split. K1: fused load+logit dot -> softmax -> attn to global
// scratch (tiny smem, ~full occupancy). K2: out[c]=sum_p patch[p,c]*attn[p],
// thread-per-output with w across lanes (coalesced rows), attn staged in smem.

#define DIMC   384
#define KWIN   7
#define PP     49
#define FINALN 16
#define HW     112
#define CPLANE (HW*HW)     // 12544
#define TPB    256
#define CSTEP  4
#define NITER  (DIMC/CSTEP)

// attn scratch: [b][h][w][64] (p padded to 64), 512 KB
__device__ float g_attn[8 * FINALN * FINALN * 64];

__global__ __launch_bounds__(TPB)
void attn_logits_kernel(const float* __restrict__ hr,
                        const float* __restrict__ du,
                        const float* __restrict__ aw,
                        const float* __restrict__ ab,
                        const float* __restrict__ wv,
                        const float* __restrict__ bv)
{
    __shared__ float saw[DIMC];
    __shared__ float sred[TPB];
    __shared__ float sattn[64];

    const int wt = blockIdx.x;
    const int h  = blockIdx.y;
    const int bb = blockIdx.z;
    const int t  = threadIdx.x;
    const int warp = t >> 5;
    const int lane = t & 31;

    for (int i = t; i < DIMC; i += TPB) saw[i] = aw[i];
    __syncthreads();

    // thread -> fixed patch slot p=t&63 (49 valid), channel c=(t>>6)+4j
    const int p   = t & 63;
    const int c0  = t >> 6;
    const bool act = (p < PP);
    const int kr  = p / KWIN;
    const int kc  = p - kr * KWIN;

    const float* gp = hr + (size_t)bb * DIMC * CPLANE
                         + (size_t)c0 * CPLANE
                         + (h * KWIN + kr) * HW + (wt * KWIN + kc);

    float lacc = 0.f;
    #pragma unroll 8
    for (int j = 0; j < NITER; ++j) {
        const float awc = saw[c0 + CSTEP * j];
        if (act) {
            const float v = gp[j * (CSTEP * CPLANE)];
            lacc = fmaf(v, awc, lacc);
        }
    }

    sred[t] = lacc;
    __syncthreads();

    if (t < 64) {
        const float l = sred[t] + sred[t + 64] + sred[t + 128] + sred[t + 192];
        if (t < PP) {
            const float maskv = (du[(bb * FINALN + h) * FINALN + wt] > 0.2f) ? 1.f : 0.f;
            sattn[t] = (l + ab[0]) * maskv * wv[t] + bv[t];
        }
    }
    __syncthreads();

    if (warp == 0) {
        const bool hi = (lane + 32) < PP;
        float v1 = sattn[lane];
        float v2 = hi ? sattn[lane + 32] : -1e30f;
        float m = fmaxf(v1, v2);
        #pragma unroll
        for (int o = 16; o; o >>= 1) m = fmaxf(m, __shfl_xor_sync(0xffffffffu, m, o));
        float e1 = __expf(v1 - m);
        float e2 = hi ? __expf(v2 - m) : 0.f;
        float s = e1 + e2;
        #pragma unroll
        for (int o = 16; o; o >>= 1) s += __shfl_xor_sync(0xffffffffu, s, o);
        const float inv = __frcp_rn(s);
        sattn[lane] = e1 * inv;
        if (hi) sattn[lane + 32] = e2 * inv;
    }
    __syncthreads();

    if (t < 64) {
        float* ga = g_attn + (((size_t)bb * FINALN + h) * FINALN + wt) * 64;
        ga[t] = (t < PP) ? sattn[t] : 0.f;
    }
}

// block: t = ty*16 + w, ty = channel sub-index (16), grid (24 cgroups, 16 h, 8 b)
__global__ __launch_bounds__(TPB)
void attn_output_kernel(const float* __restrict__ hr,
                        float* __restrict__ out)
{
    __shared__ float sattn[FINALN * 64];   // [w][64]

    const int cg = blockIdx.x;             // 0..23
    const int h  = blockIdx.y;
    const int bb = blockIdx.z;
    const int t  = threadIdx.x;
    const int w  = t & 15;
    const int ty = t >> 4;

    // stage attn for all 16 w of this (b,h): 1024 contiguous floats
    {
        const float* ga = g_attn + (((size_t)bb * FINALN + h) * FINALN) * 64;
        #pragma unroll
        for (int i = 0; i < 4; ++i) sattn[t + TPB * i] = ga[t + TPB * i];
    }
    __syncthreads();

    const int c = cg * 16 + ty;
    const float* gp = hr + ((size_t)bb * DIMC + c) * CPLANE
                         + (h * KWIN) * HW + w * KWIN;
    const float* ap = sattn + w * 64;

    float acc0 = 0.f, acc1 = 0.f;
    #pragma unroll
    for (int kr = 0; kr < KWIN; ++kr) {
        const float* row = gp + kr * HW;
        const float* arw = ap + kr * KWIN;
        acc0 = fmaf(row[0], arw[0], acc0);
        acc1 = fmaf(row[1], arw[1], acc1);
        acc0 = fmaf(row[2], arw[2], acc0);
        acc1 = fmaf(row[3], arw[3], acc1);
        acc0 = fmaf(row[4], arw[4], acc0);
        acc1 = fmaf(row[5], arw[5], acc1);
        acc0 = fmaf(row[6], arw[6], acc0);
    }

    out[((size_t)bb * DIMC + c) * (FINALN * FINALN) + h * FINALN + w] = acc0 + acc1;
}

extern "C" void kernel_launch(void* const* d_in, const int* in_sizes, int n_in,
                              void* d_out, int out_size)
{
    const float* hr = (const float*)d_in[0];   // (8,384,112,112)
    const float* du = (const float*)d_in[2];   // (8,16,16,1)
    const float* aw = (const float*)d_in[3];   // (384,)
    const float* ab = (const float*)d_in[4];   // (1,)
    const float* wv = (const float*)d_in[5];   // (7,7)
    const float* bv = (const float*)d_in[6];   // (7,7)
    float* out = (float*)d_out;                // (8,384,16,16)

    dim3 g1(FINALN, FINALN, 8);
    attn_logits_kernel<<<g1, TPB>>>(hr, du, aw, ab, wv, bv);

    dim3 g2(DIMC / 16, FINALN, 8);
    attn_output_kernel<<<g2, TPB>>>(hr, out);
}